// round 15
// baseline (speedup 1.0000x reference)
#include <cuda_runtime.h>
#include <cuda_fp16.h>
#include <mma.h>
#include <math.h>

using namespace nvcuda;

#define INC 128
#define HID 64
#define MAXN 100000
#define MAXE 1600000
#define SCAN_B 256

__device__ int    g_deg [MAXN];
__device__ int    g_incl[MAXN];
__device__ int    g_bsum[512];
__device__ int    g_rowptr[MAXN + 1];
__device__ int    g_rank[MAXE];
__device__ int    g_csrc[MAXE];
__device__ float  g_dinv[MAXN];
__device__ __half g_feat1h[(size_t)MAXN * HID];   // dinv ⊙ (x@W1) (fp16)
__device__ __half g_h1h  [(size_t)MAXN * HID];    // relu(dinv*agg1 + b1) (fp16)
__device__ __half g_feat2h[(size_t)MAXN * HID];   // dinv ⊙ (h1@W2) (fp16)

__device__ __forceinline__ void acc8_add(float* acc, uint4 w) {
    float2 f0 = __half22float2(*(__half2*)&w.x);
    float2 f1 = __half22float2(*(__half2*)&w.y);
    float2 f2 = __half22float2(*(__half2*)&w.z);
    float2 f3 = __half22float2(*(__half2*)&w.w);
    acc[0] += f0.x; acc[1] += f0.y; acc[2] += f1.x; acc[3] += f1.y;
    acc[4] += f2.x; acc[5] += f2.y; acc[6] += f3.x; acc[7] += f3.y;
}

// Degree count; atomic return value = edge's rank within its dst bucket.
__global__ void k_deg(const int* __restrict__ ei, int E) {
    int e = blockIdx.x * blockDim.x + threadIdx.x;
    if (e < E) g_rank[e] = atomicAdd(&g_deg[ei[(size_t)E + e]], 1);
}

// Pass 1: per-block inclusive scan of deg (+ dinv)
__global__ void k_scan1(int n) {
    __shared__ int s[SCAN_B];
    int i = blockIdx.x * SCAN_B + threadIdx.x;
    int v = (i < n) ? g_deg[i] : 0;
    if (i < n) g_dinv[i] = rsqrtf((float)(v + 1));   // +1 self-loop
    s[threadIdx.x] = v;
    __syncthreads();
#pragma unroll
    for (int o = 1; o < SCAN_B; o <<= 1) {
        int t = 0;
        if (threadIdx.x >= o) t = s[threadIdx.x - o];
        __syncthreads();
        s[threadIdx.x] += t;
        __syncthreads();
    }
    if (i < n) g_incl[i] = s[threadIdx.x];
    if (threadIdx.x == SCAN_B - 1) g_bsum[blockIdx.x] = s[SCAN_B - 1];
}

// Pass 2 (fused): each block reduces bsum[0..bid) itself, then writes rowptr.
__global__ void k_finalize(int n) {
    __shared__ int red[256];
    int bid = blockIdx.x;
    int t = threadIdx.x;
    int p = 0;
    if (t < bid) p = g_bsum[t];
    if (t + 256 < bid) p += g_bsum[t + 256];
    red[t] = p;
    __syncthreads();
#pragma unroll
    for (int o = 128; o > 0; o >>= 1) {
        if (t < o) red[t] += red[t + o];
        __syncthreads();
    }
    int boff = red[0];
    int i = bid * 256 + t;
    if (i < n) {
        g_rowptr[i + 1] = g_incl[i] + boff;
        if (i == 0) g_rowptr[0] = 0;
    }
}

// Atomic-free fill: pos = rowptr[dst] + rank
__global__ void k_fill(const int* __restrict__ ei, int E) {
    int e = blockIdx.x * blockDim.x + threadIdx.x;
    if (e >= E) return;
    int d = ei[(size_t)E + e];
    g_csrc[g_rowptr[d] + g_rank[e]] = ei[e];
}

// GEMM1 (WMMA fp16): g_feat1h = fp16(dinv ⊙ (x @ W1)).
__global__ __launch_bounds__(256) void k_gemm1(const float* __restrict__ x,
                                               const float* __restrict__ W,
                                               int N) {
    __shared__ __half As[128][72];
    __shared__ __half Bs[128][72];
    __shared__ float  Ps[8][16][20];
    int t = threadIdx.x;
    int wid = t >> 5, lane = t & 31;
    int row0 = blockIdx.x * 128;

    wmma::fragment<wmma::accumulator, 16, 16, 16, float> acc[4];
#pragma unroll
    for (int n = 0; n < 4; n++) wmma::fill_fragment(acc[n], 0.f);

#pragma unroll
    for (int j = 0; j < 8; j++) {
        int id = t + 256 * j;
        int kk = id >> 4, q = id & 15;
        float4 v = *(const float4*)(W + (size_t)kk * HID + q * 4);
        *(__half2*)&Bs[kk][q * 4]     = __floats2half2_rn(v.x, v.y);
        *(__half2*)&Bs[kk][q * 4 + 2] = __floats2half2_rn(v.z, v.w);
    }

#pragma unroll
    for (int kc = 0; kc < 2; kc++) {
#pragma unroll
        for (int j = 0; j < 8; j++) {
            int id = t + 256 * j;
            int r = id >> 4, q = id & 15;
            int grow = row0 + r;
            float4 v = make_float4(0.f, 0.f, 0.f, 0.f);
            if (grow < N)
                v = *(const float4*)(x + (size_t)grow * INC + kc * 64 + q * 4);
            *(__half2*)&As[r][q * 4]     = __floats2half2_rn(v.x, v.y);
            *(__half2*)&As[r][q * 4 + 2] = __floats2half2_rn(v.z, v.w);
        }
        __syncthreads();

#pragma unroll
        for (int ks = 0; ks < 4; ks++) {
            wmma::fragment<wmma::matrix_a, 16, 16, 16, __half, wmma::row_major> a;
            wmma::load_matrix_sync(a, &As[wid * 16][ks * 16], 72);
#pragma unroll
            for (int n = 0; n < 4; n++) {
                wmma::fragment<wmma::matrix_b, 16, 16, 16, __half, wmma::row_major> b;
                wmma::load_matrix_sync(b, &Bs[kc * 64 + ks * 16][n * 16], 72);
                wmma::mma_sync(acc[n], a, b, acc[n]);
            }
        }
        __syncthreads();
    }

    int r = lane >> 1, c8 = (lane & 1) * 8;
    int grow = row0 + wid * 16 + r;
    float dv = (grow < N) ? g_dinv[grow] : 0.f;
#pragma unroll
    for (int n = 0; n < 4; n++) {
        wmma::store_matrix_sync(&Ps[wid][0][0], acc[n], 20, wmma::mem_row_major);
        __syncwarp();
        if (grow < N) {
            float4 f0 = *(float4*)&Ps[wid][r][c8];
            float4 f1 = *(float4*)&Ps[wid][r][c8 + 4];
            __half2 h0 = __floats2half2_rn(f0.x * dv, f0.y * dv);
            __half2 h1 = __floats2half2_rn(f0.z * dv, f0.w * dv);
            __half2 h2 = __floats2half2_rn(f1.x * dv, f1.y * dv);
            __half2 h3 = __floats2half2_rn(f1.z * dv, f1.w * dv);
            uint4 pk = make_uint4(*(unsigned*)&h0, *(unsigned*)&h1,
                                  *(unsigned*)&h2, *(unsigned*)&h3);
            *(uint4*)(g_feat1h + (size_t)grow * HID + n * 16 + c8) = pk;
        }
        __syncwarp();
    }
}

// Layer-1 aggregate (4 edges/warp, uint4 gather) + epilogue:
// g_h1h[v] = fp16(relu(dinv[v]*acc + b1)), acc = feat1h[v] + sum feat1h[src].
__global__ __launch_bounds__(256) void k_aggregate1(const float* __restrict__ b1, int N) {
    int gtid = blockIdx.x * blockDim.x + threadIdx.x;
    int v = gtid >> 5;
    if (v >= N) return;
    int lane = threadIdx.x & 31;
    int g = lane >> 3, sub = lane & 7;
    int beg = g_rowptr[v];
    int end = g_rowptr[v + 1];

    float acc[8];
#pragma unroll
    for (int i = 0; i < 8; i++) acc[i] = 0.f;

    // Self-loop: group 0 only.
    if (g == 0)
        acc8_add(acc, *(const uint4*)(g_feat1h + (size_t)v * HID + sub * 8));

    for (int b = beg; b < end; b += 32) {
        int n = end - b;
        if (n > 32) n = 32;
        int idx = (lane < n) ? g_csrc[b + lane] : 0;
#pragma unroll 8
        for (int j4 = 0; j4 * 4 < n; j4++) {
            int e = j4 * 4 + g;
            int sj = __shfl_sync(0xffffffffu, idx, e);
            if (e < n)
                acc8_add(acc, *(const uint4*)(g_feat1h + (size_t)sj * HID + sub * 8));
        }
    }
    // Reduce across the 4 groups.
#pragma unroll
    for (int i = 0; i < 8; i++) {
        acc[i] += __shfl_xor_sync(0xffffffffu, acc[i], 8);
        acc[i] += __shfl_xor_sync(0xffffffffu, acc[i], 16);
    }
    if (g == 0) {
        float dv = g_dinv[v];
        __half2 hp[4];
#pragma unroll
        for (int i = 0; i < 4; i++) {
            float h0 = fmaxf(fmaf(acc[2 * i],     dv, __ldg(b1 + sub * 8 + 2 * i)),     0.f);
            float h1 = fmaxf(fmaf(acc[2 * i + 1], dv, __ldg(b1 + sub * 8 + 2 * i + 1)), 0.f);
            hp[i] = __floats2half2_rn(h0, h1);
        }
        uint4 pk = make_uint4(*(unsigned*)&hp[0], *(unsigned*)&hp[1],
                              *(unsigned*)&hp[2], *(unsigned*)&hp[3]);
        *(uint4*)(g_h1h + (size_t)v * HID + sub * 8) = pk;
    }
}

// GEMM2 (WMMA fp16): g_feat2h = fp16(dinv ⊙ (h1 @ W2)); A = g_h1h (fp16 direct).
__global__ __launch_bounds__(256) void k_gemm2(const float* __restrict__ W,
                                               int N) {
    __shared__ __half As[128][72];
    __shared__ __half Bs[64][72];
    __shared__ float  Ps[8][16][20];
    int t = threadIdx.x;
    int wid = t >> 5, lane = t & 31;
    int row0 = blockIdx.x * 128;

    wmma::fragment<wmma::accumulator, 16, 16, 16, float> acc[4];
#pragma unroll
    for (int n = 0; n < 4; n++) wmma::fill_fragment(acc[n], 0.f);

#pragma unroll
    for (int j = 0; j < 4; j++) {
        int id = t + 256 * j;
        int kk = id >> 4, q = id & 15;
        float4 v = *(const float4*)(W + (size_t)kk * HID + q * 4);
        *(__half2*)&Bs[kk][q * 4]     = __floats2half2_rn(v.x, v.y);
        *(__half2*)&Bs[kk][q * 4 + 2] = __floats2half2_rn(v.z, v.w);
    }

#pragma unroll
    for (int j = 0; j < 4; j++) {
        int id = t + 256 * j;
        int r = id >> 3, q = id & 7;
        int grow = row0 + r;
        uint4 v = make_uint4(0, 0, 0, 0);
        if (grow < N) v = *(const uint4*)(g_h1h + (size_t)grow * HID + q * 8);
        *(uint4*)&As[r][q * 8] = v;
    }
    __syncthreads();

#pragma unroll
    for (int ks = 0; ks < 4; ks++) {
        wmma::fragment<wmma::matrix_a, 16, 16, 16, __half, wmma::row_major> a;
        wmma::load_matrix_sync(a, &As[wid * 16][ks * 16], 72);
#pragma unroll
        for (int n = 0; n < 4; n++) {
            wmma::fragment<wmma::matrix_b, 16, 16, 16, __half, wmma::row_major> b;
            wmma::load_matrix_sync(b, &Bs[ks * 16][n * 16], 72);
            wmma::mma_sync(acc[n], a, b, acc[n]);
        }
    }

    int r = lane >> 1, c8 = (lane & 1) * 8;
    int grow = row0 + wid * 16 + r;
    float dv = (grow < N) ? g_dinv[grow] : 0.f;
#pragma unroll
    for (int n = 0; n < 4; n++) {
        wmma::store_matrix_sync(&Ps[wid][0][0], acc[n], 20, wmma::mem_row_major);
        __syncwarp();
        if (grow < N) {
            float4 f0 = *(float4*)&Ps[wid][r][c8];
            float4 f1 = *(float4*)&Ps[wid][r][c8 + 4];
            __half2 h0 = __floats2half2_rn(f0.x * dv, f0.y * dv);
            __half2 h1 = __floats2half2_rn(f0.z * dv, f0.w * dv);
            __half2 h2 = __floats2half2_rn(f1.x * dv, f1.y * dv);
            __half2 h3 = __floats2half2_rn(f1.z * dv, f1.w * dv);
            uint4 pk = make_uint4(*(unsigned*)&h0, *(unsigned*)&h1,
                                  *(unsigned*)&h2, *(unsigned*)&h3);
            *(uint4*)(g_feat2h + (size_t)grow * HID + n * 16 + c8) = pk;
        }
        __syncwarp();
    }
}

// Layer-2 aggregate (4 edges/warp) FUSED with classifier.
__global__ __launch_bounds__(256) void k_agg_out(const float* __restrict__ b2,
                                                 const float* __restrict__ Wc,
                                                 const float* __restrict__ bc,
                                                 float* __restrict__ out, int N) {
    int gtid = blockIdx.x * blockDim.x + threadIdx.x;
    int v = gtid >> 5;
    if (v >= N) return;
    int lane = threadIdx.x & 31;
    int g = lane >> 3, sub = lane & 7;
    int beg = g_rowptr[v];
    int end = g_rowptr[v + 1];

    float acc[8];
#pragma unroll
    for (int i = 0; i < 8; i++) acc[i] = 0.f;

    if (g == 0)
        acc8_add(acc, *(const uint4*)(g_feat2h + (size_t)v * HID + sub * 8));

    for (int b = beg; b < end; b += 32) {
        int n = end - b;
        if (n > 32) n = 32;
        int idx = (lane < n) ? g_csrc[b + lane] : 0;
#pragma unroll 8
        for (int j4 = 0; j4 * 4 < n; j4++) {
            int e = j4 * 4 + g;
            int sj = __shfl_sync(0xffffffffu, idx, e);
            if (e < n)
                acc8_add(acc, *(const uint4*)(g_feat2h + (size_t)sj * HID + sub * 8));
        }
    }
#pragma unroll
    for (int i = 0; i < 8; i++) {
        acc[i] += __shfl_xor_sync(0xffffffffu, acc[i], 8);
        acc[i] += __shfl_xor_sync(0xffffffffu, acc[i], 16);
    }

    float dv = g_dinv[v];
    float p = 0.f;
#pragma unroll
    for (int i = 0; i < 8; i++) {
        float h = fmaxf(fmaf(acc[i], dv, __ldg(b2 + sub * 8 + i)), 0.f);
        p = fmaf(h, __ldg(Wc + sub * 8 + i), p);
    }
    // Sum over the 8 sub-columns (each 8-lane group holds identical copies).
    p += __shfl_xor_sync(0xffffffffu, p, 1);
    p += __shfl_xor_sync(0xffffffffu, p, 2);
    p += __shfl_xor_sync(0xffffffffu, p, 4);
    if (lane == 0) out[v] = p + __ldg(bc);
}

extern "C" void kernel_launch(void* const* d_in, const int* in_sizes, int n_in,
                              void* d_out, int out_size) {
    const float* x  = (const float*)d_in[0];
    const int*   ei = (const int*)d_in[1];
    const float* W1 = (const float*)d_in[2];
    const float* b1 = (const float*)d_in[3];
    const float* W2 = (const float*)d_in[4];
    const float* b2 = (const float*)d_in[5];
    const float* Wc = (const float*)d_in[6];
    const float* bc = (const float*)d_in[7];
    float* out = (float*)d_out;

    int N = in_sizes[0] / INC;
    int E = in_sizes[1] / 2;
    int nb = (N + SCAN_B - 1) / SCAN_B;

    static cudaStream_t s2 = [] {
        cudaStream_t s; cudaStreamCreateWithFlags(&s, cudaStreamNonBlocking); return s;
    }();
    static cudaEvent_t evFork = [] {
        cudaEvent_t e; cudaEventCreateWithFlags(&e, cudaEventDisableTiming); return e;
    }();
    static cudaEvent_t evJoin = [] {
        cudaEvent_t e; cudaEventCreateWithFlags(&e, cudaEventDisableTiming); return e;
    }();

    void* degp = 0;
    cudaGetSymbolAddress(&degp, g_deg);

    // Head (main stream): deg + scan1 produce dinv (needed by gemm1 epilogue).
    cudaMemsetAsync(degp, 0, (size_t)N * sizeof(int));
    k_deg<<<(E + 255) / 256, 256>>>(ei, E);
    k_scan1<<<nb, SCAN_B>>>(N);

    // Fork: finalize+fill (CSR tail) on s2, concurrent with gemm1.
    cudaEventRecord(evFork, 0);
    cudaStreamWaitEvent(s2, evFork, 0);
    k_finalize<<<nb, 256, 0, s2>>>(N);
    k_fill<<<(E + 255) / 256, 256, 0, s2>>>(ei, E);
    cudaEventRecord(evJoin, s2);

    // Main stream: layer-1 GEMM.
    k_gemm1<<<(N + 127) / 128, 256>>>(x, W1, N);

    // Join, then the serial tail.
    cudaStreamWaitEvent(0, evJoin, 0);
    k_aggregate1<<<(N * 32 + 255) / 256, 256>>>(b1, N);
    k_gemm2<<<(N + 127) / 128, 256>>>(W2, N);
    k_agg_out<<<(N * 32 + 255) / 256, 256>>>(b2, Wc, bc, out, N);
}